// round 17
// baseline (speedup 1.0000x reference)
#include <cuda_runtime.h>
#include <cuda_fp16.h>
#include <math.h>
#include <stdint.h>

#define D_MODEL 1024
#define SEQ     4096
#define BATCH   4
#define NTOK    16384
#define NHEADS  16
#define EPS     1e-6f
#define KCH     8
#define ZS      1024.0f
#define WN      ((size_t)1024 * 1024)

// ---------------- scratch ----------------
__device__ __half g_Xh[(size_t)NTOK * D_MODEL];
__device__ __half g_Qh[(size_t)NTOK * D_MODEL];
__device__ __half g_Kh[(size_t)NTOK * D_MODEL];
__device__ __half g_Vh[(size_t)NTOK * D_MODEL];
__device__ __half g_Wh[3][(size_t)D_MODEL * D_MODEL];   // transposed [n][k]: Wq,Wk,Wv
__device__ __half g_M[BATCH][(size_t)D_MODEL * D_MODEL]; // per-batch (kv@Wo)/S, [n][k]
__device__ float  g_bkv[2 * D_MODEL];
__device__ float  g_kvp[KCH * 64 * 4096];
__device__ float  g_ksp[KCH * 64 * 64];
__device__ __half g_kvTh[64 * 4096];                    // kv^T per bh: [e][d]
__device__ float  g_ks[64 * 64];

// ---------------- fp16 TC GEMM: 256 thr, warp tile 64x32, K-tile 64 ----------------
#define RS     72
#define RSB    144
#define MATB   (128 * RSB)
#define STAGEB (2 * MATB)
#define NSTAGE 3
#define GEMM_SMEM (NSTAGE * STAGEB)
#define NKT    16

__device__ __forceinline__ void cpasync16(uint32_t dst, const void* src) {
    asm volatile("cp.async.cg.shared.global [%0], [%1], 16;\n" ::"r"(dst), "l"(src));
}

__device__ __forceinline__ void load_tile(uint32_t sst, const __half* __restrict__ A,
                                          const __half* __restrict__ Bt,
                                          int m0, int n0, int kt, int tid) {
    const __half* Asrc = A + (size_t)m0 * 1024 + kt * 64;
    const __half* Bsrc = Bt + (size_t)n0 * 1024 + kt * 64;
#pragma unroll
    for (int j = 0; j < 4; j++) {
        int c = tid + j * 256;
        int row = c >> 3, kc = (c & 7) * 8;
        cpasync16(sst + (uint32_t)(row * RSB + kc * 2), Asrc + (size_t)row * 1024 + kc);
    }
#pragma unroll
    for (int j = 0; j < 4; j++) {
        int c = tid + j * 256;
        int row = c >> 3, kc = (c & 7) * 8;
        cpasync16(sst + (uint32_t)(MATB + row * RSB + kc * 2),
                  Bsrc + (size_t)row * 1024 + kc);
    }
    asm volatile("cp.async.commit_group;\n" ::: "memory");
}

#define LDMX4(dst, addr)                                                       \
    asm volatile("ldmatrix.sync.aligned.m8n8.x4.shared.b16 {%0,%1,%2,%3}, [%4];" \
                 : "=r"((dst)[0]), "=r"((dst)[1]), "=r"((dst)[2]), "=r"((dst)[3]) \
                 : "r"(addr))

#define HMMA(acc, a, b0r, b1r)                                                 \
    asm volatile("mma.sync.aligned.m16n8k16.row.col.f32.f16.f16.f32 "          \
                 "{%0,%1,%2,%3}, {%4,%5,%6,%7}, {%8,%9}, {%0,%1,%2,%3};"       \
                 : "+f"((acc)[0]), "+f"((acc)[1]), "+f"((acc)[2]), "+f"((acc)[3]) \
                 : "r"((a)[0]), "r"((a)[1]), "r"((a)[2]), "r"((a)[3]),          \
                   "r"(b0r), "r"(b1r))

// seg 0: n0 in [0,1024) -> C0 with fmap0 ; seg 1: n0 in [1024,2048) -> C1 with fmap1
// batched: m0 += blockIdx.z*mstride ; Bt += blockIdx.z*bstride
template <typename OutT>
__global__ void __launch_bounds__(256, 2) gemm_h256(const __half* __restrict__ A,
                                                    const __half* __restrict__ Bt0,
                                                    const float* __restrict__ bias,
                                                    OutT* __restrict__ C0,
                                                    OutT* __restrict__ C1,
                                                    int fmap0, int fmap1,
                                                    int mstride, size_t bstride) {
    extern __shared__ __align__(128) char smem[];
    uint32_t sb;
    asm("{ .reg .u64 t; cvta.to.shared.u64 t, %1; cvt.u32.u64 %0, t; }" : "=r"(sb) : "l"(smem));

    const __half* Bt = Bt0 + (size_t)blockIdx.z * bstride;
    const int tid = threadIdx.x;
    const int lane = tid & 31, w = tid >> 5;
    const int wm = w & 1;
    const int wn = w >> 1;
    const int m0 = blockIdx.z * mstride + blockIdx.y * 128, n0 = blockIdx.x * 128;

    const uint32_t aOff = (uint32_t)(((wm * 64 + (lane & 15)) * RS + (lane >> 4) * 8) * 2);
    const uint32_t bOff = (uint32_t)(MATB +
                                     ((wn * 32 + ((lane >> 4) & 1) * 8 + (lane & 7)) * RS +
                                      ((lane >> 3) & 1) * 8) * 2);

    float acc[4][4][4];
#pragma unroll
    for (int i = 0; i < 4; i++)
#pragma unroll
        for (int j = 0; j < 4; j++)
#pragma unroll
            for (int r = 0; r < 4; r++) acc[i][j][r] = 0.0f;

    load_tile(sb, A, Bt, m0, n0, 0, tid);
    load_tile(sb + STAGEB, A, Bt, m0, n0, 1, tid);

    int st = 0;
    for (int kt = 0; kt < NKT; kt++) {
        if (kt < NKT - 1)
            asm volatile("cp.async.wait_group 1;\n" ::: "memory");
        else
            asm volatile("cp.async.wait_group 0;\n" ::: "memory");
        __syncthreads();
        if (kt + 2 < NKT) {
            int nst = st + 2; if (nst >= NSTAGE) nst -= NSTAGE;
            load_tile(sb + (uint32_t)nst * STAGEB, A, Bt, m0, n0, kt + 2, tid);
        }
        const uint32_t cs = sb + (uint32_t)st * STAGEB;

#pragma unroll
        for (int ks = 0; ks < 4; ks++) {
            uint32_t a[4][4];
#pragma unroll
            for (int mf = 0; mf < 4; mf++)
                LDMX4(a[mf], cs + aOff + (uint32_t)(mf * 16 * RSB + ks * 32));
#pragma unroll
            for (int nfp = 0; nfp < 2; nfp++) {
                uint32_t b[4];
                LDMX4(b, cs + bOff + (uint32_t)(nfp * 16 * RSB + ks * 32));
#pragma unroll
                for (int mf = 0; mf < 4; mf++) {
                    HMMA(acc[mf][nfp * 2], a[mf], b[0], b[1]);
                    HMMA(acc[mf][nfp * 2 + 1], a[mf], b[2], b[3]);
                }
            }
        }
        st++; if (st >= NSTAGE) st -= NSTAGE;
    }

    OutT* C = (n0 < 1024) ? C0 : C1;
    const int ncol0 = (n0 < 1024) ? n0 : n0 - 1024;
    const bool fmap = (n0 < 1024) ? (fmap0 != 0) : (fmap1 != 0);

    const int gr = lane >> 2, gc2 = (lane & 3) * 2;
#pragma unroll
    for (int mf = 0; mf < 4; mf++) {
        int r0 = m0 + wm * 64 + mf * 16 + gr;
#pragma unroll
        for (int nf = 0; nf < 4; nf++) {
            int colg = n0 + wn * 32 + nf * 8 + gc2;
            int col = ncol0 + wn * 32 + nf * 8 + gc2;
            float2 bb = *(const float2*)(bias + colg);
            float v0 = acc[mf][nf][0] + bb.x;
            float v1 = acc[mf][nf][1] + bb.y;
            float v2 = acc[mf][nf][2] + bb.x;
            float v3 = acc[mf][nf][3] + bb.y;
            if (fmap) {
                v0 = (v0 > 0.0f) ? v0 + 1.0f : expf(v0);
                v1 = (v1 > 0.0f) ? v1 + 1.0f : expf(v1);
                v2 = (v2 > 0.0f) ? v2 + 1.0f : expf(v2);
                v3 = (v3 > 0.0f) ? v3 + 1.0f : expf(v3);
            }
            if (sizeof(OutT) == 2) {
                *(__half2*)((__half*)C + (size_t)r0 * 1024 + col) = __floats2half2_rn(v0, v1);
                *(__half2*)((__half*)C + (size_t)(r0 + 8) * 1024 + col) = __floats2half2_rn(v2, v3);
            } else {
                float2 o0 = {v0, v1}, o1 = {v2, v3};
                *(float2*)((float*)C + (size_t)r0 * 1024 + col) = o0;
                *(float2*)((float*)C + (size_t)(r0 + 8) * 1024 + col) = o1;
            }
        }
    }
}

// ---------------- conversions ----------------
__global__ void to_half_kernel(const float4* __restrict__ in, __half2* __restrict__ out,
                               int n4) {
    int i = blockIdx.x * blockDim.x + threadIdx.x;
    if (i >= n4) return;
    float4 v = in[i];
    out[i * 2]     = __floats2half2_rn(v.x, v.y);
    out[i * 2 + 1] = __floats2half2_rn(v.z, v.w);
}

__global__ void transpose_half3(const float* __restrict__ W0, const float* __restrict__ W1,
                                const float* __restrict__ W2, __half* __restrict__ Wt) {
    const float* W = (blockIdx.z == 0) ? W0 : (blockIdx.z == 1) ? W1 : W2;
    __half* Wo = Wt + (size_t)blockIdx.z * D_MODEL * D_MODEL;
    __shared__ float t[32][33];
    const int bx = blockIdx.x * 32, by = blockIdx.y * 32;
    const int tx = threadIdx.x, ty = threadIdx.y;
#pragma unroll
    for (int j = 0; j < 32; j += 8)
        t[ty + j][tx] = W[(size_t)(by + ty + j) * 1024 + bx + tx];
    __syncthreads();
#pragma unroll
    for (int j = 0; j < 32; j += 8)
        Wo[(size_t)(bx + ty + j) * 1024 + by + tx] = __float2half_rn(t[tx][ty + j]);
}

__global__ void pack_bias(const float* __restrict__ bk, const float* __restrict__ bv,
                          float* __restrict__ o) {
    int i = blockIdx.x * 256 + threadIdx.x;
    if (i < 1024) o[i] = bk[i];
    else if (i < 2048) o[i] = bv[i - 1024];
}

// ---------------- kv via tensor cores (+ fused ksum partials) ----------------
#define KVST 72
__global__ void __launch_bounds__(128) kv_tc(const __half* __restrict__ Kh,
                                             const __half* __restrict__ Vh,
                                             float* __restrict__ kvp,
                                             float* __restrict__ ksp) {
    const int bh = blockIdx.x, ch = blockIdx.y;
    const int b = bh >> 4, h = bh & 15;
    __shared__ __half Ks[64 * KVST];
    __shared__ __half Vs[64 * KVST];

    const int tid = threadIdx.x;
    const int lane = tid & 31, w = tid >> 5;
    const int d0 = w * 16;
    const int g = lane >> 3, r = lane & 7;

    uint32_t ksb, vsb;
    asm("{ .reg .u64 t; cvta.to.shared.u64 t, %1; cvt.u32.u64 %0, t; }" : "=r"(ksb) : "l"(Ks));
    asm("{ .reg .u64 t; cvta.to.shared.u64 t, %1; cvt.u32.u64 %0, t; }" : "=r"(vsb) : "l"(Vs));

    const uint32_t aLane = (uint32_t)(((((g >> 1) & 1) * 8 + r) * KVST + d0 + (g & 1) * 8) * 2);
    const uint32_t bLane = (uint32_t)((((g & 1) * 8 + r) * KVST + ((g >> 1) & 1) * 8) * 2);

    float acc[8][4];
#pragma unroll
    for (int i = 0; i < 8; i++)
#pragma unroll
        for (int j = 0; j < 4; j++) acc[i][j] = 0.0f;
    float kssum = 0.0f;

    const __half* Kbase = Kh + (size_t)b * SEQ * D_MODEL + h * 64;
    const __half* Vbase = Vh + (size_t)b * SEQ * D_MODEL + h * 64;
    const int sBeg = ch * (SEQ / KCH);

    for (int t = 0; t < (SEQ / KCH) / 64; t++) {
        for (int j = 0; j < 4; j++) {
            int c = tid + j * 128;
            int row = c >> 3, col8 = (c & 7) * 8;
            const size_t gidx = (size_t)(sBeg + t * 64 + row) * 1024 + col8;
            *(uint4*)&Ks[row * KVST + col8] = *(const uint4*)(Kbase + gidx);
            *(uint4*)&Vs[row * KVST + col8] = *(const uint4*)(Vbase + gidx);
        }
        __syncthreads();

        if (tid < 64) {
#pragma unroll 8
            for (int rr = 0; rr < 64; rr++) kssum += __half2float(Ks[rr * KVST + tid]);
        }

#pragma unroll
        for (int kk = 0; kk < 4; kk++) {
            uint32_t a[4];
            uint32_t aaddr = ksb + aLane + (uint32_t)(kk * 16 * KVST * 2);
            asm volatile(
                "ldmatrix.sync.aligned.m8n8.x4.trans.shared.b16 {%0,%1,%2,%3}, [%4];"
                : "=r"(a[0]), "=r"(a[1]), "=r"(a[2]), "=r"(a[3]) : "r"(aaddr));
            uint32_t bf[8][2];
#pragma unroll
            for (int nfp = 0; nfp < 4; nfp++) {
                uint32_t baddr = vsb + bLane + (uint32_t)((kk * 16 * KVST + nfp * 16) * 2);
                asm volatile(
                    "ldmatrix.sync.aligned.m8n8.x4.trans.shared.b16 {%0,%1,%2,%3}, [%4];"
                    : "=r"(bf[nfp * 2][0]), "=r"(bf[nfp * 2][1]),
                      "=r"(bf[nfp * 2 + 1][0]), "=r"(bf[nfp * 2 + 1][1])
                    : "r"(baddr));
            }
#pragma unroll
            for (int nf = 0; nf < 8; nf++)
                HMMA(acc[nf], a, bf[nf][0], bf[nf][1]);
        }
        __syncthreads();
    }

    float* kvo = kvp + ((size_t)ch * 64 + bh) * 4096;
    const int gr = lane >> 2, gc2 = (lane & 3) * 2;
#pragma unroll
    for (int nf = 0; nf < 8; nf++) {
        int col = nf * 8 + gc2;
        *(float2*)(kvo + (d0 + gr) * 64 + col) = make_float2(acc[nf][0], acc[nf][1]);
        *(float2*)(kvo + (d0 + gr + 8) * 64 + col) = make_float2(acc[nf][2], acc[nf][3]);
    }
    if (tid < 64) ksp[((size_t)ch * 64 + bh) * 64 + tid] = kssum;
}

__global__ void reduce_kv(const float* __restrict__ kvp, const float* __restrict__ ksp,
                          __half* __restrict__ kvTh, float* __restrict__ ks) {
    int i = blockIdx.x * 256 + threadIdx.x;
    int bh = i >> 12, idx = i & 4095;
    int d = idx >> 6, e = idx & 63;
    float s = 0.f;
#pragma unroll
    for (int c = 0; c < KCH; c++) s += kvp[((size_t)c * 64 + bh) * 4096 + idx];
    kvTh[(size_t)bh * 4096 + e * 64 + d] = __float2half_rn(s);
    if (i < 64 * 64) {
        int bh2 = i >> 6, d2 = i & 63;
        float t = 0.f;
#pragma unroll
        for (int c = 0; c < KCH; c++) t += ksp[((size_t)c * 64 + bh2) * 64 + d2];
        ks[i] = t;
    }
}

// ---------------- make_M: M_b[n][h*64+d] = (sum_e kv[d,e]*Wo[h*64+e,n]) / ZS ------
// grid (64 bh, 8 nchunk of 128), 256 threads.
__global__ void __launch_bounds__(256) make_M(const __half* __restrict__ kvTh,
                                              const float* __restrict__ Wo,
                                              __half* __restrict__ M) {
    const int bh = blockIdx.x;
    const int b = bh >> 4, h = bh & 15;
    const int nc = blockIdx.y * 128;
    __shared__ float Wos[64 * 128];

    const int tid = threadIdx.x;
    const int d = tid & 63, ng = tid >> 6;   // ng 0..3

    // load Wo rows [h*64 .. h*64+64) cols [nc, nc+128) -> smem
    for (int i = tid; i < 64 * 128; i += 256) {
        int e = i >> 7, n = i & 127;
        Wos[e * 128 + n] = Wo[(size_t)(h * 64 + e) * 1024 + nc + n];
    }
    // this thread's kv row: kv[d][e] = kvTh[bh*4096 + e*64 + d]
    float kvr[64];
#pragma unroll
    for (int e = 0; e < 64; e++)
        kvr[e] = __half2float(kvTh[(size_t)bh * 4096 + e * 64 + d]);
    __syncthreads();

#pragma unroll 4
    for (int ni = 0; ni < 32; ni++) {
        int nl = ng + ni * 4;
        float acc = 0.f;
#pragma unroll
        for (int e = 0; e < 64; e++) acc += kvr[e] * Wos[e * 128 + nl];
        M[(size_t)b * WN + (size_t)(nc + nl) * 1024 + h * 64 + d] =
            __float2half_rn(acc * (1.0f / ZS));
    }
}

// ---------------- z_scale: q''[s,h*64+d] = q * ZS/(z_h(s)+eps), in-place --------
__global__ void __launch_bounds__(128) z_scale(__half* __restrict__ Qh,
                                               const float* __restrict__ ks) {
    const int row0 = blockIdx.x * 16;
    const int b = row0 / SEQ;
    __shared__ __half qsm[16 * 1024];
    __shared__ float kss[1024];
    __shared__ float zz[16 * 16];
    const int tid = threadIdx.x;

    for (int i = tid; i < 1024; i += 128) kss[i] = ks[b * 1024 + i];
    for (int i = tid; i < 16 * 128; i += 128) {
        int r = i >> 7, c8 = (i & 127) * 8;
        *(uint4*)&qsm[r * 1024 + c8] = *(const uint4*)(Qh + (size_t)(row0 + r) * 1024 + c8);
    }
    __syncthreads();

    for (int p = tid; p < 256; p += 128) {
        int r = p >> 4, h = p & 15;
        float z = 0.f;
#pragma unroll 8
        for (int d = 0; d < 64; d++)
            z += __half2float(qsm[r * 1024 + h * 64 + d]) * kss[h * 64 + d];
        zz[r * 16 + h] = ZS / (z + EPS);
    }
    __syncthreads();

    for (int i = tid; i < 16 * 128; i += 128) {
        int r = i >> 7, c8 = (i & 127) * 8;
        float sc = zz[r * 16 + (c8 >> 6)];
        uint4 v = *(uint4*)&qsm[r * 1024 + c8];
        __half2* hv = (__half2*)&v;
        uint4 o;
        __half2* ho = (__half2*)&o;
#pragma unroll
        for (int j = 0; j < 4; j++) {
            float2 f = __half22float2(hv[j]);
            ho[j] = __floats2half2_rn(f.x * sc, f.y * sc);
        }
        *(uint4*)(Qh + (size_t)(row0 + r) * 1024 + c8) = o;
    }
}

// ---------------- launch ----------------
extern "C" void kernel_launch(void* const* d_in, const int* in_sizes, int n_in,
                              void* d_out, int out_size) {
    const float* x  = (const float*)d_in[0];
    const float* Wq = (const float*)d_in[1];
    const float* bq = (const float*)d_in[2];
    const float* Wk = (const float*)d_in[3];
    const float* bk = (const float*)d_in[4];
    const float* Wv = (const float*)d_in[5];
    const float* bv = (const float*)d_in[6];
    const float* Wo = (const float*)d_in[7];
    const float* bo = (const float*)d_in[8];
    float* out = (float*)d_out;

    __half *Xh, *Qh, *Kh, *Vh, *Wh, *kvTh, *Mp;
    float *bkv, *kvp, *ksp, *ks;
    cudaGetSymbolAddress((void**)&Xh, g_Xh);
    cudaGetSymbolAddress((void**)&Qh, g_Qh);
    cudaGetSymbolAddress((void**)&Kh, g_Kh);
    cudaGetSymbolAddress((void**)&Vh, g_Vh);
    cudaGetSymbolAddress((void**)&Wh, g_Wh);
    cudaGetSymbolAddress((void**)&kvTh, g_kvTh);
    cudaGetSymbolAddress((void**)&Mp, g_M);
    cudaGetSymbolAddress((void**)&bkv, g_bkv);
    cudaGetSymbolAddress((void**)&kvp, g_kvp);
    cudaGetSymbolAddress((void**)&ksp, g_ksp);
    cudaGetSymbolAddress((void**)&ks, g_ks);

    cudaFuncSetAttribute(gemm_h256<__half>, cudaFuncAttributeMaxDynamicSharedMemorySize,
                         GEMM_SMEM);
    cudaFuncSetAttribute(gemm_h256<float>, cudaFuncAttributeMaxDynamicSharedMemorySize,
                         GEMM_SMEM);

    static cudaStream_t s1 = nullptr;
    static cudaEvent_t evPre = nullptr, evQ = nullptr, evKS = nullptr, evZ = nullptr;
    if (s1 == nullptr) {
        cudaStreamCreate(&s1);
        cudaEventCreateWithFlags(&evPre, cudaEventDisableTiming);
        cudaEventCreateWithFlags(&evQ, cudaEventDisableTiming);
        cudaEventCreateWithFlags(&evKS, cudaEventDisableTiming);
        cudaEventCreateWithFlags(&evZ, cudaEventDisableTiming);
    }

    const size_t W1 = (size_t)D_MODEL * D_MODEL;

    to_half_kernel<<<NTOK * D_MODEL / 4 / 256, 256>>>((const float4*)x, (__half2*)Xh,
                                                      NTOK * D_MODEL / 4);
    transpose_half3<<<dim3(32, 32, 3), dim3(32, 8)>>>(Wq, Wk, Wv, Wh);
    pack_bias<<<8, 256>>>(bk, bv, bkv);

    // fork: Q projection on side stream, KV projection + kv chain on main stream
    cudaEventRecord(evPre, 0);
    cudaStreamWaitEvent(s1, evPre, 0);
    gemm_h256<__half><<<dim3(8, 128), 256, GEMM_SMEM, s1>>>(Xh, Wh + 0 * W1, bq,
                                                            Qh, Qh, 1, 1, 0, 0);
    cudaEventRecord(evQ, s1);

    gemm_h256<__half><<<dim3(16, 128), 256, GEMM_SMEM>>>(Xh, Wh + 1 * W1, bkv,
                                                         Kh, Vh, 1, 0, 0, 0);
    kv_tc<<<dim3(64, KCH), 128>>>(Kh, Vh, kvp, ksp);
    reduce_kv<<<(64 * 4096) / 256, 256>>>(kvp, ksp, kvTh, ks);
    cudaEventRecord(evKS, 0);

    // z_scale on s1 (needs Q + ks); make_M on main (needs kvTh + Wo) — concurrent
    cudaStreamWaitEvent(s1, evKS, 0);
    z_scale<<<NTOK / 16, 128, 0, s1>>>(Qh, ks);
    cudaEventRecord(evZ, s1);

    make_M<<<dim3(64, 8), 256>>>(kvTh, Wo, Mp);

    cudaStreamWaitEvent(0, evZ, 0);
    // out = q'' @ M_b + bo, batched over z (per-batch M)
    gemm_h256<float><<<dim3(8, 32, 4), 256, GEMM_SMEM>>>(Qh, Mp, bo, out, out, 0, 0,
                                                         4096, W1);
}